// round 17
// baseline (speedup 1.0000x reference)
#include <cuda_runtime.h>
#include <math.h>

#define NTOK 8192
#define DDIM 1024
#define NEXP 16
#define GRP  8               // tokens per group
#define NGRPS 4              // groups per block
#define TPB  (GRP * NGRPS)   // 32 tokens per block
#define NBLK (NTOK / TPB)    // 256 blocks
#define FULL 0xffffffffu
#define HBUF (GRP * DDIM)    // floats per h buffer
#define LSTR 20              // logit_s row stride (16B-aligned rows)

typedef unsigned long long u64;

// ---- scratch (device globals: no allocation allowed) ----
__device__ float g_S[DDIM];          // column sums of h^2 ; zero at load, re-zeroed by moe_loss
__device__ float g_G[NEXP * NEXP];   // Gram accumulator; zero at load, re-zeroed by moe_loss

__device__ __forceinline__ void cpasync16(float* dst, const float* src) {
    unsigned d = (unsigned)__cvta_generic_to_shared(dst);
    asm volatile("cp.async.cg.shared.global [%0], [%1], 16;" :: "r"(d), "l"(src));
}
__device__ __forceinline__ void cp_commit() { asm volatile("cp.async.commit_group;"); }
__device__ __forceinline__ void cp_wait1()  { asm volatile("cp.async.wait_group 1;"); }

// ---- packed f32x2 helpers (PTX-only; ptxas won't auto-fuse) ----
__device__ __forceinline__ u64 fma2(u64 a, u64 b, u64 c) {
    u64 d; asm("fma.rn.f32x2 %0, %1, %2, %3;" : "=l"(d) : "l"(a), "l"(b), "l"(c)); return d;
}
__device__ __forceinline__ u64 mul2(u64 a, u64 b) {
    u64 d; asm("mul.rn.f32x2 %0, %1, %2;" : "=l"(d) : "l"(a), "l"(b)); return d;
}
__device__ __forceinline__ u64 add2(u64 a, u64 b) {
    u64 d; asm("add.rn.f32x2 %0, %1, %2;" : "=l"(d) : "l"(a), "l"(b)); return d;
}
__device__ __forceinline__ u64 pack2(float lo, float hi) {
    u64 d; asm("mov.b64 %0, {%1, %2};" : "=l"(d) : "f"(lo), "f"(hi)); return d;
}
__device__ __forceinline__ void unpack2(u64 v, float& lo, float& hi) {
    asm("mov.b64 {%0, %1}, %2;" : "=f"(lo), "=f"(hi) : "l"(v));
}

// ============================================================================
// K1: fused router + combine (R16 structure; combine token-pair batched,
//   router row read as 4x LDS.128). Triple-buffered cp.async h staging,
//   2 blocks/SM, gate register-resident packed, packed f32x2 math.
// ============================================================================
extern "C" __global__ void __launch_bounds__(256, 2)
moe_main(const float* __restrict__ x,
         const float* __restrict__ gate_w,
         const float* __restrict__ gate_b,
         const float* __restrict__ sh_e,
         const float* __restrict__ rt_e,
         float* __restrict__ out)
{
    extern __shared__ float h_s[];                    // 3 * 32 KB
    __shared__ __align__(16) float logit_s[GRP * LSTR];

    const int tid  = threadIdx.x;
    const int warp = tid >> 5;
    const int lane = tid & 31;
    const int tok0 = blockIdx.x * TPB;

    // ---- prefetch groups 0 and 1 ----
    #pragma unroll
    for (int i = 0; i < 8; i++)
        cpasync16(&h_s[0 * HBUF + 4 * (i * 256 + tid)],
                  x + (size_t)tok0 * DDIM + 4 * (i * 256 + tid));
    cp_commit();
    #pragma unroll
    for (int i = 0; i < 8; i++)
        cpasync16(&h_s[1 * HBUF + 4 * (i * 256 + tid)],
                  x + (size_t)(tok0 + GRP) * DDIM + 4 * (i * 256 + tid));
    cp_commit();

    // ---- gate rows 2*warp, 2*warp+1 as packed pairs ----
    ulonglong2 gA2[8], gB2[8];
    {
        const ulonglong2* gwp = (const ulonglong2*)(gate_w + 2 * warp * DDIM) + lane;
        #pragma unroll
        for (int i = 0; i < 8; i++) {
            gA2[i] = gwp[32 * i];
            gB2[i] = gwp[256 + 32 * i];
        }
    }
    const float biasA = __ldg(&gate_b[2 * warp]);
    const float biasB = __ldg(&gate_b[2 * warp + 1]);

    // ---- combine dim-slice + shared-expert sum (packed) ----
    const int d0 = 128 * warp + 4 * lane;
    u64 sh01, sh23;
    {
        ulonglong2 a = *(const ulonglong2*)(sh_e + d0);
        ulonglong2 b = *(const ulonglong2*)(sh_e + DDIM + d0);
        sh01 = add2(a.x, b.x);
        sh23 = add2(a.y, b.y);
    }
    u64 s2a = 0ull, s2b = 0ull;            // packed h^2 partials

    #pragma unroll
    for (int grp = 0; grp < NGRPS; grp++) {
        const int tbase = tok0 + grp * GRP;
        const float* hbuf = h_s + (grp % 3) * HBUF;

        cp_wait1();          // group `grp` landed
        __syncthreads();     // visible to all; all warps past group grp-1 combine

        // ---- early prefetch grp+2 into buffer (grp+2)%3 ----
        if (grp + 2 < NGRPS) {
            const float* src = x + (size_t)(tok0 + (grp + 2) * GRP) * DDIM;
            float* dst = h_s + ((grp + 2) % 3) * HBUF;
            #pragma unroll
            for (int i = 0; i < 8; i++)
                cpasync16(&dst[4 * (i * 256 + tid)], src + 4 * (i * 256 + tid));
        }
        cp_commit();         // commit every group to keep wait-counts aligned

        // ---- logits: 2 experts x 8 tokens, packed f32x2, two 4-token passes ----
        #pragma unroll
        for (int p = 0; p < 2; p++) {
            u64 aA[4], aB[4];
            #pragma unroll
            for (int t = 0; t < 4; t++) { aA[t] = 0ull; aB[t] = 0ull; }
            #pragma unroll
            for (int i = 0; i < 8; i++) {
                const u64 ga01 = gA2[i].x, ga23 = gA2[i].y;
                const u64 gb01 = gB2[i].x, gb23 = gB2[i].y;
                #pragma unroll
                for (int t = 0; t < 4; t++) {
                    ulonglong2 h2 = *(const ulonglong2*)
                        &hbuf[(4 * p + t) * DDIM + 4 * lane + 128 * i];
                    aA[t] = fma2(ga01, h2.x, aA[t]);
                    aA[t] = fma2(ga23, h2.y, aA[t]);
                    aB[t] = fma2(gb01, h2.x, aB[t]);
                    aB[t] = fma2(gb23, h2.y, aB[t]);
                }
            }
            // horizontal add of packed halves -> 8 scalars (j = 2*t + esub)
            float acc[8];
            #pragma unroll
            for (int t = 0; t < 4; t++) {
                float lo, hi;
                unpack2(aA[t], lo, hi); acc[2 * t]     = lo + hi;
                unpack2(aB[t], lo, hi); acc[2 * t + 1] = lo + hi;
            }
            // reduce-scatter 8 values over 32 lanes;
            // final: lanes with (lane&3)==0 hold j = 4*b4 + 2*b3 + b2
            float v4[4];
            #pragma unroll
            for (int j = 0; j < 4; j++) {
                float send = (lane & 16) ? acc[j] : acc[j + 4];
                float recv = __shfl_xor_sync(FULL, send, 16);
                v4[j] = ((lane & 16) ? acc[j + 4] : acc[j]) + recv;
            }
            float v2[2];
            #pragma unroll
            for (int j = 0; j < 2; j++) {
                float s2 = (lane & 8) ? v4[j] : v4[j + 2];
                float r2 = __shfl_xor_sync(FULL, s2, 8);
                v2[j] = ((lane & 8) ? v4[j + 2] : v4[j]) + r2;
            }
            float s1 = (lane & 4) ? v2[0] : v2[1];
            float r1 = __shfl_xor_sync(FULL, s1, 4);
            float z  = ((lane & 4) ? v2[1] : v2[0]) + r1;
            z += __shfl_xor_sync(FULL, z, 2);
            z += __shfl_xor_sync(FULL, z, 1);

            if ((lane & 3) == 0) {
                const int j = 4 * ((lane >> 4) & 1) + 2 * ((lane >> 3) & 1) + ((lane >> 2) & 1);
                const int esub = j & 1;
                logit_s[(4 * p + (j >> 1)) * LSTR + 2 * warp + esub]
                    = z + (esub ? biasB : biasA);
            }
        }
        __syncthreads();

        // ---- router: 4x LDS.128 row read, register scan; lane -> token lane&7 ----
        const int t_r = lane & 7;
        float lg[16];
        {
            const float4* row = (const float4*)&logit_s[t_r * LSTR];
            float4 a = row[0], b = row[1], c = row[2], d = row[3];
            lg[0]=a.x; lg[1]=a.y; lg[2]=a.z; lg[3]=a.w;
            lg[4]=b.x; lg[5]=b.y; lg[6]=b.z; lg[7]=b.w;
            lg[8]=c.x; lg[9]=c.y; lg[10]=c.z; lg[11]=c.w;
            lg[12]=d.x; lg[13]=d.y; lg[14]=d.z; lg[15]=d.w;
        }
        float v1 = -1e30f, vv2 = -1e30f; int j1 = 0, j2 = 0;
        #pragma unroll
        for (int e = 0; e < NEXP; e++) {
            if (lg[e] > v1)       { vv2 = v1; j2 = j1; v1 = lg[e]; j1 = e; }
            else if (lg[e] > vv2) { vv2 = lg[e]; j2 = e; }
        }
        const float w0s = 1.f / (1.f + __expf(vv2 - v1));   // softmax denom cancels
        const int mypk = j1 | (j2 << 8);                    // packed indices

        // ---- combine (dim-sliced, packed), token-pair batched ----
        #pragma unroll
        for (int q = 0; q < 4; q++) {
            const int ta = 2 * q, tb = 2 * q + 1;
            // shfls for both tokens (independent, pipelined)
            const float w0A = __shfl_sync(FULL, w0s, ta);
            const float w0B = __shfl_sync(FULL, w0s, tb);
            const int   pA  = __shfl_sync(FULL, mypk, ta);
            const int   pB  = __shfl_sync(FULL, mypk, tb);
            // all 6 memory ops issued back-to-back (MLP 6)
            ulonglong2 r0A = __ldg((const ulonglong2*)(rt_e + (pA & 0xff) * DDIM + d0));
            ulonglong2 r1A = __ldg((const ulonglong2*)(rt_e + ((pA >> 8) & 0xff) * DDIM + d0));
            ulonglong2 r0B = __ldg((const ulonglong2*)(rt_e + (pB & 0xff) * DDIM + d0));
            ulonglong2 r1B = __ldg((const ulonglong2*)(rt_e + ((pB >> 8) & 0xff) * DDIM + d0));
            ulonglong2 hA  = *(const ulonglong2*)&hbuf[ta * DDIM + d0];
            ulonglong2 hB  = *(const ulonglong2*)&hbuf[tb * DDIM + d0];
            // math + stores
            const u64 w0pA = pack2(w0A, w0A), w1pA = pack2(1.f - w0A, 1.f - w0A);
            const u64 w0pB = pack2(w0B, w0B), w1pB = pack2(1.f - w0B, 1.f - w0B);
            ulonglong2 oA, oB;
            oA.x = mul2(hA.x, fma2(w1pA, r1A.x, fma2(w0pA, r0A.x, sh01)));
            oA.y = mul2(hA.y, fma2(w1pA, r1A.y, fma2(w0pA, r0A.y, sh23)));
            oB.x = mul2(hB.x, fma2(w1pB, r1B.x, fma2(w0pB, r0B.x, sh01)));
            oB.y = mul2(hB.y, fma2(w1pB, r1B.y, fma2(w0pB, r0B.y, sh23)));
            *(ulonglong2*)(out + (size_t)(tbase + ta) * DDIM + d0) = oA;
            *(ulonglong2*)(out + (size_t)(tbase + tb) * DDIM + d0) = oB;
            s2a = fma2(hA.x, hA.x, s2a);
            s2b = fma2(hA.y, hA.y, s2b);
            s2a = fma2(hB.x, hB.x, s2a);
            s2b = fma2(hB.y, hB.y, s2b);
        }
        // no end-of-group barrier: next group's first barrier protects buffers
    }

    {
        float sx, sy, sz, sw;
        unpack2(s2a, sx, sy);
        unpack2(s2b, sz, sw);
        atomicAdd(&g_S[d0 + 0], sx);
        atomicAdd(&g_S[d0 + 1], sy);
        atomicAdd(&g_S[d0 + 2], sz);
        atomicAdd(&g_S[d0 + 3], sw);
    }
}

// ============================================================================
// K2: d-parallel Gram. 64 blocks own 16-dim slices; thread = (e,f) pair;
//   smem-staged rt slice (pad 17) + S slice; one atomicAdd into g_G.
// ============================================================================
#define GBLK 64
#define GDIM (DDIM / GBLK)   // 16 dims per block

extern "C" __global__ void __launch_bounds__(256, 4)
moe_gram(const float* __restrict__ rt_e)
{
    __shared__ float rs[NEXP * 17];   // [e][j], padded
    __shared__ float Ss[GDIM];
    const int tid = threadIdx.x;
    const int dbase = blockIdx.x * GDIM;

    {
        const int e = tid >> 4, j = tid & 15;
        rs[e * 17 + j] = __ldg(&rt_e[e * DDIM + dbase + j]);
        if (tid < GDIM) Ss[tid] = g_S[dbase + tid];
    }
    __syncthreads();

    const int e = tid >> 4, f = tid & 15;
    float acc = 0.f;
    #pragma unroll
    for (int j = 0; j < GDIM; j++)
        acc += rs[e * 17 + j] * rs[f * 17 + j] * Ss[j];
    atomicAdd(&g_G[tid], acc);
}

// ============================================================================
// K3: final diversity loss (g_G row preloaded, MLP=16); 256-thread re-zero
//   of g_S/g_G for next graph replay.
// ============================================================================
extern "C" __global__ void __launch_bounds__(256)
moe_loss(float* __restrict__ out, int has_loss, int loss_idx)
{
    const int tid = threadIdx.x;

    if (tid < 32) {
        const int lane = tid;
        const int e = lane & 15;
        float gv[NEXP];
        #pragma unroll
        for (int f = 0; f < NEXP; f++) gv[f] = __ldg(&g_G[e * NEXP + f]);

        float n = sqrtf(gv[e]);
        n = fmaxf(n, 1e-8f);
        float s = 0.f;
        #pragma unroll
        for (int f = 0; f < NEXP; f++) {
            float nf = __shfl_sync(FULL, n, f);
            if (f != e) {
                float sim = gv[f] / (n * nf);
                sim = fminf(1.f, fmaxf(-1.f, sim));
                s += sim;
            }
        }
        if (lane >= 16) s = 0.f;
        #pragma unroll
        for (int off = 16; off; off >>= 1) s += __shfl_xor_sync(FULL, s, off);
        if (lane == 0 && has_loss)
            out[loss_idx] = s / (float)(NEXP * (NEXP - 1)) * 0.1f;
    }

    __syncthreads();
    for (int i = tid; i < DDIM; i += 256) g_S[i] = 0.f;
    if (tid < NEXP * NEXP) g_G[tid] = 0.f;
}

// ============================================================================
extern "C" void kernel_launch(void* const* d_in, const int* in_sizes, int n_in,
                              void* d_out, int out_size)
{
    const float* x  = (const float*)d_in[0];
    const float* gw = (const float*)d_in[1];
    const float* gb = (const float*)d_in[2];
    const float* se = (const float*)d_in[3];
    const float* re = (const float*)d_in[4];
    float* out = (float*)d_out;

    const int SMEM1 = 3 * HBUF * (int)sizeof(float);   // 96 KB dynamic
    cudaFuncSetAttribute((const void*)moe_main,
                         cudaFuncAttributeMaxDynamicSharedMemorySize, SMEM1);

    moe_main<<<NBLK, 256, SMEM1>>>(x, gw, gb, se, re, out);
    moe_gram<<<GBLK, 256>>>(re);

    int has_loss = (out_size > NTOK * DDIM) ? 1 : 0;
    moe_loss<<<1, 256>>>(out, has_loss, out_size - 1);
}